// round 1
// baseline (speedup 1.0000x reference)
#include <cuda_runtime.h>
#include <math_constants.h>

// Problem dims (fixed by setup_inputs)
#define BB 32
#define TT 2048
#define DD 1024
#define SPLITS 64
#define TC (TT / SPLITS)      // 32 rows per block
#define RPI 4                 // rows per iteration
#define NTHR 256              // = DD/4 (one float4 lane per thread)

// Scratch (no cudaMalloc allowed)
__device__ float g_scores[BB * TT];
__device__ float g_part_m[BB * SPLITS];
__device__ float g_part_z[BB * SPLITS];
__device__ float g_part_c[(size_t)BB * SPLITS * DD];
__device__ float g_M[BB];
__device__ float g_Z[BB];

// ---------------------------------------------------------------------------
// Pass 1: fused dot-product + online softmax accumulation over a T-chunk.
// One block = (split, batch). Each thread owns a float4 slice of D.
// ---------------------------------------------------------------------------
__global__ __launch_bounds__(NTHR) void dpa_pass1(const float* __restrict__ q,
                                                  const float* __restrict__ v) {
    const int split = blockIdx.x;
    const int b     = blockIdx.y;
    const int tid   = threadIdx.x;
    const int lane  = tid & 31;
    const int warp  = tid >> 5;

    __shared__ float red[8][RPI];

    // q slice in registers
    const float4 q4 = reinterpret_cast<const float4*>(q + (size_t)b * DD)[tid];

    float  m = -CUDART_INF_F;
    float  Z = 0.0f;
    float4 c = make_float4(0.f, 0.f, 0.f, 0.f);

    const int t0 = split * TC;
    const float* vb = v + (size_t)b * TT * DD;

    for (int it = 0; it < TC; it += RPI) {
        // Load RPI rows (coalesced float4) and partial dots
        float4 vv[RPI];
        float  p[RPI];
#pragma unroll
        for (int r = 0; r < RPI; r++) {
            vv[r] = reinterpret_cast<const float4*>(vb + (size_t)(t0 + it + r) * DD)[tid];
            p[r]  = q4.x * vv[r].x + q4.y * vv[r].y + q4.z * vv[r].z + q4.w * vv[r].w;
        }
        // Warp reduce each of the RPI partials
#pragma unroll
        for (int r = 0; r < RPI; r++) {
#pragma unroll
            for (int o = 16; o > 0; o >>= 1)
                p[r] += __shfl_xor_sync(0xffffffffu, p[r], o);
        }
        if (lane == 0) {
#pragma unroll
            for (int r = 0; r < RPI; r++) red[warp][r] = p[r];
        }
        __syncthreads();

        float s[RPI];
#pragma unroll
        for (int r = 0; r < RPI; r++) {
            float acc = 0.f;
#pragma unroll
            for (int w = 0; w < 8; w++) acc += red[w][r];
            s[r] = acc;
        }
        __syncthreads();  // before smem reuse next iter

        // Stash raw scores (threads 0..RPI-1)
        if (tid < RPI) g_scores[b * TT + t0 + it + tid] = s[tid];

        // Online softmax update (identical scalar math on all threads)
        float nm = m;
#pragma unroll
        for (int r = 0; r < RPI; r++) nm = fmaxf(nm, s[r]);
        const float f = __expf(m - nm);   // 0 on first iter (m = -inf)
        Z *= f;
        c.x *= f; c.y *= f; c.z *= f; c.w *= f;
#pragma unroll
        for (int r = 0; r < RPI; r++) {
            const float e = __expf(s[r] - nm);
            Z  += e;
            c.x += e * vv[r].x;
            c.y += e * vv[r].y;
            c.z += e * vv[r].z;
            c.w += e * vv[r].w;
        }
        m = nm;
    }

    // Write per-split partials
    reinterpret_cast<float4*>(g_part_c + (size_t)(b * SPLITS + split) * DD)[tid] = c;
    if (tid == 0) {
        g_part_m[b * SPLITS + split] = m;
        g_part_z[b * SPLITS + split] = Z;
    }
}

// ---------------------------------------------------------------------------
// Pass 2: combine split partials per batch; write context to d_out.
// ---------------------------------------------------------------------------
__global__ __launch_bounds__(NTHR) void dpa_pass2(float* __restrict__ out_ctx) {
    const int b   = blockIdx.x;
    const int tid = threadIdx.x;

    // global max over splits (redundant per thread — tiny)
    float M = -CUDART_INF_F;
#pragma unroll 8
    for (int j = 0; j < SPLITS; j++) M = fmaxf(M, g_part_m[b * SPLITS + j]);

    float  Zt = 0.f;
    float4 c  = make_float4(0.f, 0.f, 0.f, 0.f);
    for (int j = 0; j < SPLITS; j++) {
        const float e = __expf(g_part_m[b * SPLITS + j] - M);
        Zt += g_part_z[b * SPLITS + j] * e;
        const float4 pc =
            reinterpret_cast<const float4*>(g_part_c + (size_t)(b * SPLITS + j) * DD)[tid];
        c.x += e * pc.x; c.y += e * pc.y; c.z += e * pc.z; c.w += e * pc.w;
    }
    const float inv = 1.0f / Zt;
    float4 o;
    o.x = c.x * inv; o.y = c.y * inv; o.z = c.z * inv; o.w = c.w * inv;
    reinterpret_cast<float4*>(out_ctx + (size_t)b * DD)[tid] = o;

    if (tid == 0) { g_M[b] = M; g_Z[b] = Zt; }
}

// ---------------------------------------------------------------------------
// Pass 3: attention weights = exp(s - M) / Z
// ---------------------------------------------------------------------------
__global__ __launch_bounds__(NTHR) void dpa_pass3(float* __restrict__ out_w) {
    const int idx = blockIdx.x * NTHR + threadIdx.x;  // < BB*TT
    const int b   = idx / TT;
    out_w[idx] = __expf(g_scores[idx] - g_M[b]) / g_Z[b];
}

extern "C" void kernel_launch(void* const* d_in, const int* in_sizes, int n_in,
                              void* d_out, int out_size) {
    const float* q = (const float*)d_in[0];   // [32,1024]
    const float* v = (const float*)d_in[1];   // [32,2048,1024]
    float* out = (float*)d_out;               // context [32*1024] ++ weights [32*2048]

    dpa_pass1<<<dim3(SPLITS, BB), NTHR>>>(q, v);
    dpa_pass2<<<BB, NTHR>>>(out);
    dpa_pass3<<<(BB * TT) / NTHR, NTHR>>>(out + (size_t)BB * DD);
}

// round 2
// speedup vs baseline: 1.2517x; 1.2517x over previous
#include <cuda_runtime.h>
#include <math_constants.h>

// Problem dims (fixed by setup_inputs)
#define BB 32
#define TT 2048
#define DD 1024
#define SPLITS 32
#define TC (TT / SPLITS)      // 64 rows per pass1 block
#define RPI 8                 // rows per iteration (2 barriers per 8 rows)
#define NTHR 256              // = DD/4 (one float4 lane per thread)

// Scratch (no cudaMalloc allowed)
__device__ float g_scores[BB * TT];
__device__ float g_part_m[BB * SPLITS];
__device__ float g_part_z[BB * SPLITS];
__device__ float g_part_c[(size_t)BB * SPLITS * DD];
__device__ float g_M[BB];
__device__ float g_Z[BB];

// ---------------------------------------------------------------------------
// Pass 1: fused dot-product + online softmax accumulation over a T-chunk.
// One block = (split, batch). Each thread owns a float4 slice of D.
// Rows are kept in registers so values is read exactly once.
// ---------------------------------------------------------------------------
__global__ __launch_bounds__(NTHR) void dpa_pass1(const float* __restrict__ q,
                                                  const float* __restrict__ v) {
    const int split = blockIdx.x;
    const int b     = blockIdx.y;
    const int tid   = threadIdx.x;
    const int lane  = tid & 31;
    const int warp  = tid >> 5;

    __shared__ float red[8][RPI];

    const float4 q4 = reinterpret_cast<const float4*>(q + (size_t)b * DD)[tid];

    float  m = -CUDART_INF_F;
    float  Z = 0.0f;
    float4 c = make_float4(0.f, 0.f, 0.f, 0.f);

    const int t0 = split * TC;
    const float* vb = v + (size_t)b * TT * DD;

    for (int it = 0; it < TC; it += RPI) {
        float4 vv[RPI];
        float  p[RPI];
#pragma unroll
        for (int r = 0; r < RPI; r++) {
            vv[r] = reinterpret_cast<const float4*>(vb + (size_t)(t0 + it + r) * DD)[tid];
            p[r]  = q4.x * vv[r].x + q4.y * vv[r].y + q4.z * vv[r].z + q4.w * vv[r].w;
        }
#pragma unroll
        for (int r = 0; r < RPI; r++) {
#pragma unroll
            for (int o = 16; o > 0; o >>= 1)
                p[r] += __shfl_xor_sync(0xffffffffu, p[r], o);
        }
        if (lane == 0) {
#pragma unroll
            for (int r = 0; r < RPI; r++) red[warp][r] = p[r];
        }
        __syncthreads();

        float s[RPI];
#pragma unroll
        for (int r = 0; r < RPI; r++) {
            float acc = 0.f;
#pragma unroll
            for (int w = 0; w < 8; w++) acc += red[w][r];
            s[r] = acc;
        }
        __syncthreads();  // before smem reuse next iter

        if (tid < RPI) g_scores[b * TT + t0 + it + tid] = s[tid];

        // Online softmax update (identical scalar math on all threads)
        float nm = m;
#pragma unroll
        for (int r = 0; r < RPI; r++) nm = fmaxf(nm, s[r]);
        const float f = __expf(m - nm);   // 0 on first iter (m = -inf)
        Z *= f;
        c.x *= f; c.y *= f; c.z *= f; c.w *= f;
#pragma unroll
        for (int r = 0; r < RPI; r++) {
            const float e = __expf(s[r] - nm);
            Z  += e;
            c.x += e * vv[r].x;
            c.y += e * vv[r].y;
            c.z += e * vv[r].z;
            c.w += e * vv[r].w;
        }
        m = nm;
    }

    reinterpret_cast<float4*>(g_part_c + (size_t)(b * SPLITS + split) * DD)[tid] = c;
    if (tid == 0) {
        g_part_m[b * SPLITS + split] = m;
        g_part_z[b * SPLITS + split] = Z;
    }
}

// ---------------------------------------------------------------------------
// Pass 2a: per-batch global max M and normalizer Z from the 32 split partials.
// One warp per batch. Tiny.
// ---------------------------------------------------------------------------
__global__ __launch_bounds__(32) void dpa_pass2a() {
    const int b = blockIdx.x;
    const int j = threadIdx.x;                 // SPLITS == 32 == warp size
    const float mj = g_part_m[b * SPLITS + j];
    float M = mj;
#pragma unroll
    for (int o = 16; o > 0; o >>= 1) M = fmaxf(M, __shfl_xor_sync(0xffffffffu, M, o));
    float z = g_part_z[b * SPLITS + j] * __expf(mj - M);
#pragma unroll
    for (int o = 16; o > 0; o >>= 1) z += __shfl_xor_sync(0xffffffffu, z, o);
    if (j == 0) { g_M[b] = M; g_Z[b] = z; }
}

// ---------------------------------------------------------------------------
// Pass 2b: combine split context partials. One thread per output element,
// 128 blocks -> full-chip parallelism, split loop fully unrolled (MLP=32).
// ---------------------------------------------------------------------------
__global__ __launch_bounds__(NTHR) void dpa_pass2b(float* __restrict__ out_ctx) {
    const int b   = blockIdx.y;
    const int d   = blockIdx.x * NTHR + threadIdx.x;   // 4 blocks of 256 cover D=1024

    __shared__ float se[SPLITS];
    if (threadIdx.x < SPLITS)
        se[threadIdx.x] = __expf(g_part_m[b * SPLITS + threadIdx.x] - g_M[b]);
    __syncthreads();

    const float* pc = g_part_c + (size_t)b * SPLITS * DD + d;
    float acc = 0.f;
#pragma unroll
    for (int j = 0; j < SPLITS; j++)
        acc += se[j] * pc[(size_t)j * DD];

    out_ctx[(size_t)b * DD + d] = acc / g_Z[b];
}

// ---------------------------------------------------------------------------
// Pass 3: attention weights = exp(s - M) / Z
// ---------------------------------------------------------------------------
__global__ __launch_bounds__(NTHR) void dpa_pass3(float* __restrict__ out_w) {
    const int idx = blockIdx.x * NTHR + threadIdx.x;  // < BB*TT
    const int b   = idx >> 11;                        // TT = 2048
    out_w[idx] = __expf(g_scores[idx] - g_M[b]) / g_Z[b];
}

extern "C" void kernel_launch(void* const* d_in, const int* in_sizes, int n_in,
                              void* d_out, int out_size) {
    const float* q = (const float*)d_in[0];   // [32,1024]
    const float* v = (const float*)d_in[1];   // [32,2048,1024]
    float* out = (float*)d_out;               // context [32*1024] ++ weights [32*2048]

    dpa_pass1<<<dim3(SPLITS, BB), NTHR>>>(q, v);
    dpa_pass2a<<<BB, 32>>>();
    dpa_pass2b<<<dim3(DD / NTHR, BB), NTHR>>>(out);
    dpa_pass3<<<(BB * TT) / NTHR, NTHR>>>(out + (size_t)BB * DD);
}

// round 3
// speedup vs baseline: 1.2896x; 1.0303x over previous
#include <cuda_runtime.h>
#include <math_constants.h>

// Problem dims (fixed by setup_inputs)
#define BB 32
#define TT 2048
#define DD 1024
#define SPLITS 32
#define TC (TT / SPLITS)      // 64 rows per pass1 block
#define RPI 4                 // rows per iteration
#define NTHR 256              // = DD/4 (one float4 lane per thread)

// Scratch (no cudaMalloc allowed)
__device__ float g_scores[BB * TT];
__device__ float g_part_m[BB * SPLITS];
__device__ float g_part_z[BB * SPLITS];
__device__ float g_part_c[(size_t)BB * SPLITS * DD];

// ---------------------------------------------------------------------------
// Pass 1: fused dot-product + online softmax accumulation over a T-chunk.
// One block = (split, batch). Each thread owns a float4 slice of D.
// Software-pipelined: next iteration's rows are loaded before the reduction
// barriers so HBM stays saturated through the sync bubbles.
// ---------------------------------------------------------------------------
__global__ __launch_bounds__(NTHR) void dpa_pass1(const float* __restrict__ q,
                                                  const float* __restrict__ v) {
    const int split = blockIdx.x;
    const int b     = blockIdx.y;
    const int tid   = threadIdx.x;
    const int lane  = tid & 31;
    const int warp  = tid >> 5;

    __shared__ float red[8][RPI];

    const float4 q4 = reinterpret_cast<const float4*>(q + (size_t)b * DD)[tid];

    float  m = -CUDART_INF_F;
    float  Z = 0.0f;
    float4 c = make_float4(0.f, 0.f, 0.f, 0.f);

    const int t0 = split * TC;
    const float4* vb = reinterpret_cast<const float4*>(v + (size_t)b * TT * DD) + tid;

    // prologue: load first RPI rows
    float4 vv[RPI];
#pragma unroll
    for (int r = 0; r < RPI; r++)
        vv[r] = vb[(size_t)(t0 + r) * (DD / 4)];

    for (int it = 0; it < TC; it += RPI) {
        const bool more = (it + RPI) < TC;

        // prefetch next RPI rows (independent loads — stay in flight through barriers)
        float4 nx[RPI];
        if (more) {
#pragma unroll
            for (int r = 0; r < RPI; r++)
                nx[r] = vb[(size_t)(t0 + it + RPI + r) * (DD / 4)];
        }

        // partial dots on current rows
        float p[RPI];
#pragma unroll
        for (int r = 0; r < RPI; r++)
            p[r] = q4.x * vv[r].x + q4.y * vv[r].y + q4.z * vv[r].z + q4.w * vv[r].w;

        // warp reduce
#pragma unroll
        for (int r = 0; r < RPI; r++) {
#pragma unroll
            for (int o = 16; o > 0; o >>= 1)
                p[r] += __shfl_xor_sync(0xffffffffu, p[r], o);
        }
        if (lane == 0) {
#pragma unroll
            for (int r = 0; r < RPI; r++) red[warp][r] = p[r];
        }
        __syncthreads();

        float s[RPI];
#pragma unroll
        for (int r = 0; r < RPI; r++) {
            float acc = 0.f;
#pragma unroll
            for (int w = 0; w < 8; w++) acc += red[w][r];
            s[r] = acc;
        }
        __syncthreads();  // before smem reuse next iter

        if (tid < RPI) g_scores[b * TT + t0 + it + tid] = s[tid];

        // Online softmax update (identical scalar math on all threads)
        float nm = m;
#pragma unroll
        for (int r = 0; r < RPI; r++) nm = fmaxf(nm, s[r]);
        const float f = __expf(m - nm);   // 0 on first iter (m = -inf)
        Z *= f;
        c.x *= f; c.y *= f; c.z *= f; c.w *= f;
#pragma unroll
        for (int r = 0; r < RPI; r++) {
            const float e = __expf(s[r] - nm);
            Z  += e;
            c.x += e * vv[r].x;
            c.y += e * vv[r].y;
            c.z += e * vv[r].z;
            c.w += e * vv[r].w;
        }
        m = nm;

        if (more) {
#pragma unroll
            for (int r = 0; r < RPI; r++) vv[r] = nx[r];
        }
    }

    reinterpret_cast<float4*>(g_part_c + (size_t)(b * SPLITS + split) * DD)[tid] = c;
    if (tid == 0) {
        g_part_m[b * SPLITS + split] = m;
        g_part_z[b * SPLITS + split] = Z;
    }
}

// ---------------------------------------------------------------------------
// Tail (single kernel): every block redundantly derives M,Z for its batch
// from the 32 split partials (L2-resident), then either combines context
// partials (blockIdx.x 0..3) or writes attention weights (blockIdx.x 4..11).
// ---------------------------------------------------------------------------
__global__ __launch_bounds__(NTHR) void dpa_tail(float* __restrict__ out) {
    const int b    = blockIdx.y;
    const int part = blockIdx.x;   // 0..11
    const int tid  = threadIdx.x;

    __shared__ float sM, sZ, se[SPLITS];

    if (tid < SPLITS) {
        const float mj = g_part_m[b * SPLITS + tid];
        float M = mj;
#pragma unroll
        for (int o = 16; o > 0; o >>= 1)
            M = fmaxf(M, __shfl_xor_sync(0xffffffffu, M, o));
        float z = g_part_z[b * SPLITS + tid] * __expf(mj - M);
#pragma unroll
        for (int o = 16; o > 0; o >>= 1)
            z += __shfl_xor_sync(0xffffffffu, z, o);
        se[tid] = __expf(mj - M);
        if (tid == 0) { sM = M; sZ = z; }
    }
    __syncthreads();

    if (part < 4) {
        // context: one output element per thread, split loop fully unrolled
        const int d = part * NTHR + tid;
        const float* pc = g_part_c + (size_t)b * SPLITS * DD + d;
        float acc = 0.f;
#pragma unroll
        for (int j = 0; j < SPLITS; j++)
            acc += se[j] * pc[(size_t)j * DD];
        out[(size_t)b * DD + d] = acc / sZ;
    } else {
        // weights: exp(s - M) / Z
        const int i = (part - 4) * NTHR + tid;           // < TT
        out[(size_t)BB * DD + (size_t)b * TT + i] =
            __expf(g_scores[b * TT + i] - sM) / sZ;
    }
}

extern "C" void kernel_launch(void* const* d_in, const int* in_sizes, int n_in,
                              void* d_out, int out_size) {
    const float* q = (const float*)d_in[0];   // [32,1024]
    const float* v = (const float*)d_in[1];   // [32,2048,1024]
    float* out = (float*)d_out;               // context [32*1024] ++ weights [32*2048]

    dpa_pass1<<<dim3(SPLITS, BB), NTHR>>>(q, v);
    dpa_tail<<<dim3(12, BB), NTHR>>>(out);
}